// round 3
// baseline (speedup 1.0000x reference)
#include <cuda_runtime.h>
#include <cuda_bf16.h>

#define Nn 50000
#define Ee 800000
#define ET (Ee + Nn)       // edges + self loops
#define F_IN 16
#define Hh 8
#define Cc 16
#define HID 128
#define NEG_SLOPE 0.2f

// ---------------- scratch (no allocations allowed) ----------------
__device__ float g_h0[Nn * HID];     // ping
__device__ float g_h1[Nn * HID];     // pong
__device__ float g_alS[Nn * Hh];
__device__ float g_alD[Nn * Hh];
__device__ int   g_deg[Nn];
__device__ int   g_rowptr[Nn + 1];
__device__ int   g_cursor[Nn];
__device__ int   g_csrsrc[ET];
__device__ int   g_bsum[128];

// ---------------- CSR build ----------------
__global__ void k_clear() {
    int i = blockIdx.x * blockDim.x + threadIdx.x;
    if (i < Nn) g_deg[i] = 0;
}

// edge_index arrives as int32 (JAX default config downcasts int64 -> int32).
__global__ void k_hist(const int* __restrict__ ei) {
    int e = blockIdx.x * blockDim.x + threadIdx.x;
    if (e >= ET) return;
    int d = (e < Ee) ? ei[Ee + e] : (e - Ee);
    atomicAdd(&g_deg[d], 1);
}

#define SB 512
#define NB ((Nn + SB - 1) / SB)   // 98

__global__ void k_scan_a() {
    __shared__ int sm[SB];
    int b = blockIdx.x, t = threadIdx.x;
    int i = b * SB + t;
    int v = (i < Nn) ? g_deg[i] : 0;
    sm[t] = v;
    __syncthreads();
    for (int o = 1; o < SB; o <<= 1) {
        int u = (t >= o) ? sm[t - o] : 0;
        __syncthreads();
        sm[t] += u;
        __syncthreads();
    }
    if (i < Nn) g_rowptr[i] = sm[t] - v;   // local exclusive
    if (t == SB - 1) g_bsum[b] = sm[t];
}

__global__ void k_scan_b() {
    __shared__ int sm[128];
    int t = threadIdx.x;
    sm[t] = (t < NB) ? g_bsum[t] : 0;
    __syncthreads();
    for (int o = 1; o < 128; o <<= 1) {
        int u = (t >= o) ? sm[t - o] : 0;
        __syncthreads();
        sm[t] += u;
        __syncthreads();
    }
    if (t < NB) g_bsum[t] = sm[t];   // inclusive
}

__global__ void k_scan_c() {
    int b = blockIdx.x, t = threadIdx.x;
    int i = b * SB + t;
    if (i < Nn) {
        int off = (b > 0) ? g_bsum[b - 1] : 0;
        int r = g_rowptr[i] + off;
        g_rowptr[i] = r;
        g_cursor[i] = r;
    }
    if (b == 0 && t == 0) g_rowptr[Nn] = ET;
}

__global__ void k_scatter(const int* __restrict__ ei) {
    int e = blockIdx.x * blockDim.x + threadIdx.x;
    if (e >= ET) return;
    int d, s;
    if (e < Ee) { s = ei[e]; d = ei[Ee + e]; }
    else        { s = e - Ee; d = e - Ee; }
    int pos = atomicAdd(&g_cursor[d], 1);
    g_csrsrc[pos] = s;
}

// ---------------- GEMM + attention logit kernel ----------------
// Block: 128 threads, computes 32 rows x 128 cols.
// Thread (cx = tid%32, ry = tid/32) holds 8 rows x 4 cols.
// hin_sel: 0 = external x pointer, 1 = g_h1.  hout always g_h0.
template <int FIN>
__global__ __launch_bounds__(128) void gemm_al_kernel(
    const float* __restrict__ xext, const float* __restrict__ W,
    const float* __restrict__ aS, const float* __restrict__ aD,
    int hin_sel)
{
    constexpr int KT = 16;
    __shared__ float Ws[KT][HID];
    __shared__ float xs[KT][32];
    const float* __restrict__ x = (hin_sel == 0) ? xext : g_h1;
    float* __restrict__ hout = g_h0;

    int tid = threadIdx.x;
    int cx = tid & 31, ry = tid >> 5;
    int r0 = blockIdx.x * 32;
    float acc[8][4] = {};

    for (int kt = 0; kt < FIN; kt += KT) {
#pragma unroll
        for (int k = 0; k < KT; k++) Ws[k][tid] = W[(kt + k) * HID + tid];
#pragma unroll
        for (int it = 0; it < 4; it++) {
            int lin = tid + it * 128;      // 512 elements = 32 rows * 16 k
            int r = lin >> 4, k = lin & 15;
            int row = r0 + r;
            xs[k][r] = (row < Nn) ? x[row * FIN + kt + k] : 0.f;
        }
        __syncthreads();
#pragma unroll
        for (int k = 0; k < KT; k++) {
            float4 w4 = *(const float4*)&Ws[k][cx * 4];
#pragma unroll
            for (int r = 0; r < 8; r++) {
                float xv = xs[k][ry * 8 + r];
                acc[r][0] += xv * w4.x;
                acc[r][1] += xv * w4.y;
                acc[r][2] += xv * w4.z;
                acc[r][3] += xv * w4.w;
            }
        }
        __syncthreads();
    }

    int hd = cx >> 2;    // head of this thread's 4 columns
    float a_s[4], a_d[4];
#pragma unroll
    for (int j = 0; j < 4; j++) {
        int c = (cx * 4 + j) & 15;
        a_s[j] = aS[hd * 16 + c];
        a_d[j] = aD[hd * 16 + c];
    }
#pragma unroll
    for (int r = 0; r < 8; r++) {
        int row = r0 + ry * 8 + r;
        if (row >= Nn) break;   // uniform across the warp (r0+ry*8 spans whole warp)
        float4 hv = make_float4(acc[r][0], acc[r][1], acc[r][2], acc[r][3]);
        *(float4*)&hout[row * HID + cx * 4] = hv;
        float ps = acc[r][0] * a_s[0] + acc[r][1] * a_s[1] + acc[r][2] * a_s[2] + acc[r][3] * a_s[3];
        float pd = acc[r][0] * a_d[0] + acc[r][1] * a_d[1] + acc[r][2] * a_d[2] + acc[r][3] * a_d[3];
        ps += __shfl_xor_sync(0xffffffffu, ps, 1);
        ps += __shfl_xor_sync(0xffffffffu, ps, 2);
        pd += __shfl_xor_sync(0xffffffffu, pd, 1);
        pd += __shfl_xor_sync(0xffffffffu, pd, 2);
        if ((cx & 3) == 0) {
            g_alS[row * Hh + hd] = ps;
            g_alD[row * Hh + hd] = pd;
        }
    }
}

// ---------------- Edge kernel: online softmax + aggregation + bias + elu ----------------
// One block (128 threads) per destination node. Thread tid owns output channel tid.
// Reads h from g_h0, writes out to g_h1.
#define CH 16
__global__ __launch_bounds__(128) void edge_agg_kernel(const float* __restrict__ b)
{
    const float* __restrict__ h = g_h0;
    float* __restrict__ out = g_h1;

    int d = blockIdx.x;
    int tid = threadIdx.x;
    __shared__ int   s_src[CH];
    __shared__ float s_w[CH][Hh];
    __shared__ float s_m[Hh], s_s[Hh], s_scale[Hh], s_ald[Hh], s_cm[Hh];

    int beg = g_rowptr[d], end = g_rowptr[d + 1];
    if (tid < Hh) {
        s_m[tid] = -1e30f;
        s_s[tid] = 0.f;
        s_ald[tid] = g_alD[d * Hh + tid];
    }
    __syncthreads();

    float acc = 0.f;
    int hd = tid >> 4;
    int i = tid >> 3, hh = tid & 7;

    for (int base = beg; base < end; base += CH) {
        int cnt = min(CH, end - base);
        if (tid < cnt) s_src[tid] = g_csrsrc[base + tid];
        __syncthreads();

        float lg = -1e30f;
        if (i < cnt) {
            float v = g_alS[s_src[i] * Hh + hh] + s_ald[hh];
            lg = (v > 0.f) ? v : NEG_SLOPE * v;
        }
        s_w[i][hh] = lg;
        __syncthreads();

        if (tid < Hh) {
            float mx = s_m[tid];
            for (int j = 0; j < cnt; j++) mx = fmaxf(mx, s_w[j][tid]);
            s_scale[tid] = __expf(s_m[tid] - mx);
            s_cm[tid] = mx;
        }
        __syncthreads();

        float w = 0.f;
        if (i < cnt) w = __expf(lg - s_cm[hh]);
        s_w[i][hh] = w;
        __syncthreads();

        if (tid < Hh) {
            float ss = s_s[tid] * s_scale[tid];
            for (int j = 0; j < cnt; j++) ss += s_w[j][tid];
            s_s[tid] = ss;
            s_m[tid] = s_cm[tid];
        }

        acc *= s_scale[hd];
#pragma unroll 4
        for (int j = 0; j < cnt; j++)
            acc += s_w[j][hd] * h[s_src[j] * HID + tid];
        __syncthreads();
    }

    float o = acc / s_s[hd] + b[tid];
    out[d * HID + tid] = (o > 0.f) ? o : (__expf(o) - 1.f);  // elu
}

// ---------------- Final fc: [N,128] @ [128,1] + b (reads g_h1) ----------------
__global__ void fc_kernel(const float* __restrict__ w, const float* __restrict__ bb,
                          float* __restrict__ out)
{
    const float* __restrict__ h = g_h1;
    int node = blockIdx.x * 4 + (threadIdx.x >> 5);
    int lane = threadIdx.x & 31;
    if (node >= Nn) return;
    float s = 0.f;
#pragma unroll
    for (int c = lane; c < HID; c += 32) s += h[node * HID + c] * w[c];
#pragma unroll
    for (int o = 16; o; o >>= 1) s += __shfl_xor_sync(0xffffffffu, s, o);
    if (lane == 0) out[node] = s + bb[0];
}

// ---------------- launch ----------------
extern "C" void kernel_launch(void* const* d_in, const int* in_sizes, int n_in,
                              void* d_out, int out_size)
{
    const float* x   = (const float*)d_in[0];
    const int*   ei  = (const int*)d_in[1];   // int32: JAX downcasts int64 by default
    const float* W1  = (const float*)d_in[2];
    const float* a1s = (const float*)d_in[3];
    const float* a1d = (const float*)d_in[4];
    const float* b1  = (const float*)d_in[5];
    const float* W2  = (const float*)d_in[6];
    const float* a2s = (const float*)d_in[7];
    const float* a2d = (const float*)d_in[8];
    const float* b2  = (const float*)d_in[9];
    const float* W3  = (const float*)d_in[10];
    const float* a3s = (const float*)d_in[11];
    const float* a3d = (const float*)d_in[12];
    const float* b3  = (const float*)d_in[13];
    const float* fcw = (const float*)d_in[14];
    const float* fcb = (const float*)d_in[15];
    float* out = (float*)d_out;

    // CSR build (graph is identical across layers)
    k_clear<<<(Nn + 255) / 256, 256>>>();
    k_hist<<<(ET + 255) / 256, 256>>>(ei);
    k_scan_a<<<NB, SB>>>();
    k_scan_b<<<1, 128>>>();
    k_scan_c<<<NB, SB>>>();
    k_scatter<<<(ET + 255) / 256, 256>>>(ei);

    int gemm_blocks = (Nn + 31) / 32;

    // layer 1: x -> h (g_h0), edges -> elu out (g_h1)
    gemm_al_kernel<F_IN><<<gemm_blocks, 128>>>(x, W1, a1s, a1d, /*hin=*/0);
    edge_agg_kernel<<<Nn, 128>>>(b1);

    // layer 2: g_h1 -> h (g_h0), edges -> g_h1
    gemm_al_kernel<HID><<<gemm_blocks, 128>>>(nullptr, W2, a2s, a2d, /*hin=*/1);
    edge_agg_kernel<<<Nn, 128>>>(b2);

    // layer 3: g_h1 -> h (g_h0), edges -> g_h1
    gemm_al_kernel<HID><<<gemm_blocks, 128>>>(nullptr, W3, a3s, a3d, /*hin=*/1);
    edge_agg_kernel<<<Nn, 128>>>(b3);

    // head
    fc_kernel<<<(Nn + 3) / 4, 128>>>(fcw, fcb, out);
}